// round 12
// baseline (speedup 1.0000x reference)
#include <cuda_runtime.h>
#include <cuda_bf16.h>
#include <math.h>
#include <stdint.h>

// Problem constants (fixed shapes)
#define NROWS 16384     // B*T (GEMM M)
#define CDIM  512       // phones (GEMM K)
#define ADIM  4096      // arcs
#define PDIM  256       // phonemes (GEMM N)

// ---------------- device scratch ----------------
__device__ __nv_bfloat16 g_M[PDIM * CDIM];   // dense matrix [p][c] (= B col-major), 256 KB

// ---------------- build dense M (256 blocks x 256 threads) ----------------
#define FXSCALE 16777216.0f
__global__ void __launch_bounds__(256) k_buildM(const float* __restrict__ alloW,
                                                const int* __restrict__ phone,
                                                const int* __restrict__ phoneme) {
    __shared__ int rowi[CDIM];
    const int p = blockIdx.x, t = threadIdx.x;
    rowi[t] = 0;
    rowi[t + 256] = 0;
    __syncthreads();

#pragma unroll 4
    for (int a = t; a < ADIM; a += 256) {
        if (phoneme[a] == p) {
            int fx = __float2int_rn(expf(alloW[a]) * FXSCALE);
            atomicAdd(&rowi[phone[a]], fx);
        }
    }
    __syncthreads();

    g_M[p * CDIM + t]       = __float2bfloat16_rn((float)rowi[t] * (1.0f / FXSCALE));
    g_M[p * CDIM + t + 256] = __float2bfloat16_rn((float)rowi[t + 256] * (1.0f / FXSCALE));
}

// ---------------- fused exp+GEMM+epilogue (256 blocks x 256, occ 2) ----------------
// Tile 64x256. K processed in two halves of 256; sA holds one half (unnormalized exp).
// smem: sA [64][264] bf16 = 33792 | sB 2 x [256][72] bf16 = 73728 | s_inv 256  -> 107776 B
#define MROWS 64
#define LDA2  264
#define LDB   72
#define KC    64
#define NKC   8
#define SA_BYTES (MROWS * LDA2 * 2)
#define SB_BYTES (256 * LDB * 2)
#define SM_INV   (SA_BYTES + 2 * SB_BYTES)
#define SMEM_GEMM (SM_INV + 256)

__device__ __forceinline__ void mma16816(float* d, const uint32_t* a, const uint32_t* b) {
    asm volatile("mma.sync.aligned.m16n8k16.row.col.f32.bf16.bf16.f32 "
                 "{%0,%1,%2,%3}, {%4,%5,%6,%7}, {%8,%9}, {%0,%1,%2,%3};"
                 : "+f"(d[0]), "+f"(d[1]), "+f"(d[2]), "+f"(d[3])
                 : "r"(a[0]), "r"(a[1]), "r"(a[2]), "r"(a[3]), "r"(b[0]), "r"(b[1]));
}
__device__ __forceinline__ void ldsm_x4(uint32_t* r, uint32_t addr) {
    asm volatile("ldmatrix.sync.aligned.m8n8.x4.shared.b16 {%0,%1,%2,%3}, [%4];"
                 : "=r"(r[0]), "=r"(r[1]), "=r"(r[2]), "=r"(r[3]) : "r"(addr));
}
__device__ __forceinline__ void ldsm_x2(uint32_t* r, uint32_t addr) {
    asm volatile("ldmatrix.sync.aligned.m8n8.x2.shared.b16 {%0,%1}, [%2];"
                 : "=r"(r[0]), "=r"(r[1]) : "r"(addr));
}
__device__ __forceinline__ uint32_t smem_u32(const void* p) {
    uint32_t a;
    asm("{ .reg .u64 t; cvta.to.shared.u64 t, %1; cvt.u32.u64 %0, t; }" : "=r"(a) : "l"(p));
    return a;
}
__device__ __forceinline__ void cp16(uint32_t dst, const void* src) {
    asm volatile("cp.async.cg.shared.global [%0], [%1], 16;" :: "r"(dst), "l"(src));
}
#define CP_COMMIT() asm volatile("cp.async.commit_group;" ::: "memory")

__global__ void __launch_bounds__(256, 2) k_gemm(const float* __restrict__ hs,
                                                 float* __restrict__ out) {
    extern __shared__ char smem[];
    __nv_bfloat16* sA    = (__nv_bfloat16*)smem;               // [64][LDA2] (one K-half)
    float*         s_inv = (float*)(smem + SM_INV);            // [64]
    float*         s_rs  = (float*)smem;                       // reuse sA after mainloop

    const int tid  = threadIdx.x;
    const int warp = tid >> 5, lane = tid & 31;
    const int wm = warp >> 2, wn = warp & 3;   // 2 x 4 warp grid (32-row x 64-col warp tiles)
    const int g = lane >> 2, t = lane & 3;
    const int row0 = blockIdx.x * MROWS;
    const uint32_t sA_u32 = smem_u32(smem);
    const uint32_t sB_u32 = sA_u32 + SA_BYTES;

    // ldmatrix lane-address components
    const int a_row  = wm * 32 + (lane & 15);
    const int a_csel = (lane >> 4) << 3;
    const int b_row  = wn * 64 + (lane & 7);
    const int b_csel = (lane & 8);

    // ---- prefetch B chunk 0 ----
    for (int i = tid; i < 2048; i += 256) {
        int r = i >> 3, c = i & 7;
        cp16(sB_u32 + r * (LDB * 2) + c * 16, g_M + (size_t)r * CDIM + c * 8);
    }
    CP_COMMIT();

    float lane_part[8];
#pragma unroll
    for (int j = 0; j < 8; j++) lane_part[j] = 0.0f;

    const float* hwarp = hs + (size_t)(row0 + warp * 8) * CDIM;

    // ---- softmax half 0 (cols 0..255), unnormalized exp ----
#pragma unroll 1
    for (int b = 0; b < 2; b++) {
        float4 v[4][2];
#pragma unroll
        for (int i = 0; i < 4; i++) {
            const float4* hp = (const float4*)(hwarp + (size_t)(b * 4 + i) * CDIM);
#pragma unroll
            for (int s = 0; s < 2; s++) v[i][s] = hp[s * 32 + lane];
        }
#pragma unroll
        for (int i = 0; i < 4; i++) {
            const int row = warp * 8 + b * 4 + i;
#pragma unroll
            for (int s = 0; s < 2; s++) {
                float e0 = __expf(v[i][s].x), e1 = __expf(v[i][s].y);
                float e2 = __expf(v[i][s].z), e3 = __expf(v[i][s].w);
                lane_part[b * 4 + i] += (e0 + e1) + (e2 + e3);
                __nv_bfloat162 p0 = __floats2bfloat162_rn(e0, e1);
                __nv_bfloat162 p1 = __floats2bfloat162_rn(e2, e3);
                uint2 w;
                w.x = *(uint32_t*)&p0;
                w.y = *(uint32_t*)&p1;
                *(uint2*)(sA + row * LDA2 + s * 128 + lane * 4) = w;
            }
        }
    }

    float acc[2][8][4];
#pragma unroll
    for (int mi = 0; mi < 2; mi++)
#pragma unroll
        for (int ni = 0; ni < 8; ni++)
#pragma unroll
            for (int f = 0; f < 4; f++) acc[mi][ni][f] = 0.0f;

    // ---- mainloop: 8 K-chunks of 64; softmax half 1 injected before chunk 4 ----
#pragma unroll 1
    for (int kc = 0; kc < NKC; kc++) {
        if (kc == 4) {
            // group-local barrier: this wm-group's chunk-3 sA reads are done
            asm volatile("bar.sync %0, 128;" :: "r"(wm + 1) : "memory");
            // softmax half 1 (cols 256..511) into sA
#pragma unroll 1
            for (int b = 0; b < 2; b++) {
                float4 v[4][2];
#pragma unroll
                for (int i = 0; i < 4; i++) {
                    const float4* hp = (const float4*)(hwarp + (size_t)(b * 4 + i) * CDIM + 256);
#pragma unroll
                    for (int s = 0; s < 2; s++) v[i][s] = hp[s * 32 + lane];
                }
#pragma unroll
                for (int i = 0; i < 4; i++) {
                    const int row = warp * 8 + b * 4 + i;
#pragma unroll
                    for (int s = 0; s < 2; s++) {
                        float e0 = __expf(v[i][s].x), e1 = __expf(v[i][s].y);
                        float e2 = __expf(v[i][s].z), e3 = __expf(v[i][s].w);
                        lane_part[b * 4 + i] += (e0 + e1) + (e2 + e3);
                        __nv_bfloat162 p0 = __floats2bfloat162_rn(e0, e1);
                        __nv_bfloat162 p1 = __floats2bfloat162_rn(e2, e3);
                        uint2 w;
                        w.x = *(uint32_t*)&p0;
                        w.y = *(uint32_t*)&p1;
                        *(uint2*)(sA + row * LDA2 + s * 128 + lane * 4) = w;
                    }
                }
            }
            // finalize row sums -> s_inv
#pragma unroll
            for (int j = 0; j < 8; j++) {
                float v = lane_part[j];
#pragma unroll
                for (int o = 16; o; o >>= 1) v += __shfl_xor_sync(0xffffffffu, v, o);
                if (lane == 0) s_inv[warp * 8 + j] = 1.0f / v;
            }
        }

        asm volatile("cp.async.wait_group 0;" ::: "memory");
        __syncthreads();  // publishes B chunk kc (+ sA half on kc==0/4); proves prior MMA done

        if (kc + 1 < NKC) {
            for (int i = tid; i < 2048; i += 256) {
                int r = i >> 3, c = i & 7;
                cp16(sB_u32 + ((kc + 1) & 1) * SB_BYTES + r * (LDB * 2) + c * 16,
                     g_M + (size_t)r * CDIM + (kc + 1) * KC + c * 8);
            }
            CP_COMMIT();
        }

        const uint32_t sBbuf = sB_u32 + (kc & 1) * SB_BYTES;
#pragma unroll
        for (int kt = 0; kt < 4; kt++) {
            const int kcol = (kc & 3) * KC + kt * 16;
            uint32_t afr[2][4], bfr[8][2];
#pragma unroll
            for (int mi = 0; mi < 2; mi++)
                ldsm_x4(afr[mi], sA_u32 + ((a_row + mi * 16) * LDA2 + kcol + a_csel) * 2);
#pragma unroll
            for (int ni = 0; ni < 8; ni++)
                ldsm_x2(bfr[ni], sBbuf + ((b_row + ni * 8) * LDB + kt * 16 + b_csel) * 2);
#pragma unroll
            for (int mi = 0; mi < 2; mi++)
#pragma unroll
                for (int ni = 0; ni < 8; ni++)
                    mma16816(acc[mi][ni], afr[mi], bfr[ni]);
        }
    }
    __syncthreads();  // mainloop done; sA reusable as s_rs

    // ---- epilogue: per-row totals (raw), fold 1/rowsum ----
    float psum[2][2];
#pragma unroll
    for (int mi = 0; mi < 2; mi++) {
        float s0 = 0.0f, s1 = 0.0f;
#pragma unroll
        for (int ni = 0; ni < 8; ni++) {
            s0 += acc[mi][ni][0] + acc[mi][ni][1];
            s1 += acc[mi][ni][2] + acc[mi][ni][3];
        }
        s0 += __shfl_xor_sync(0xffffffffu, s0, 1);
        s0 += __shfl_xor_sync(0xffffffffu, s0, 2);
        s1 += __shfl_xor_sync(0xffffffffu, s1, 1);
        s1 += __shfl_xor_sync(0xffffffffu, s1, 2);
        psum[mi][0] = s0;
        psum[mi][1] = s1;
    }
    if (t == 0) {
#pragma unroll
        for (int mi = 0; mi < 2; mi++) {
            s_rs[wn * MROWS + wm * 32 + mi * 16 + g]     = psum[mi][0];
            s_rs[wn * MROWS + wm * 32 + mi * 16 + g + 8] = psum[mi][1];
        }
    }
    __syncthreads();

#pragma unroll
    for (int mi = 0; mi < 2; mi++) {
        const int lr0 = wm * 32 + mi * 16 + g;
        const float inv0 = s_inv[lr0], inv1 = s_inv[lr0 + 8];
        float tot0 = s_rs[lr0] + s_rs[MROWS + lr0] + s_rs[2 * MROWS + lr0] + s_rs[3 * MROWS + lr0];
        float tot1 = s_rs[lr0 + 8] + s_rs[MROWS + lr0 + 8] + s_rs[2 * MROWS + lr0 + 8] + s_rs[3 * MROWS + lr0 + 8];
        float red0 = (tot0 * inv0 - 1.0f) * (1.0f / (float)PDIM);
        float red1 = (tot1 * inv1 - 1.0f) * (1.0f / (float)PDIM);
        float* o0 = out + (size_t)(row0 + lr0) * PDIM;
        float* o1 = out + (size_t)(row0 + lr0 + 8) * PDIM;
#pragma unroll
        for (int ni = 0; ni < 8; ni++) {
            const int col = wn * 64 + ni * 8 + 2 * t;
            float2 v0, v1;
            v0.x = __logf(acc[mi][ni][0] * inv0 - red0);
            v0.y = __logf(acc[mi][ni][1] * inv0 - red0);
            v1.x = __logf(acc[mi][ni][2] * inv1 - red1);
            v1.y = __logf(acc[mi][ni][3] * inv1 - red1);
            *(float2*)(o0 + col) = v0;
            *(float2*)(o1 + col) = v1;
        }
    }
}

// ---------------- launch ----------------
extern "C" void kernel_launch(void* const* d_in, const int* in_sizes, int n_in,
                              void* d_out, int out_size) {
    const float* hs      = (const float*)d_in[0];
    const float* alloW   = (const float*)d_in[1];
    const int*   phone   = (const int*)d_in[2];
    const int*   phoneme = (const int*)d_in[3];
    float*       out     = (float*)d_out;
    (void)in_sizes; (void)n_in; (void)out_size;

    static bool attr_set = false;
    if (!attr_set) {
        cudaFuncSetAttribute(k_gemm, cudaFuncAttributeMaxDynamicSharedMemorySize, SMEM_GEMM);
        attr_set = true;
    }

    k_buildM<<<PDIM, 256>>>(alloW, phone, phoneme);
    k_gemm<<<NROWS / MROWS, 256, SMEM_GEMM>>>(hs, out);
}